// round 3
// baseline (speedup 1.0000x reference)
#include <cuda_runtime.h>
#include <cstdint>
#include <math.h>

#define D_IN_   128
#define D_HID_  256
#define TILE_M  128           // edges per tile
#define NTHREADS 512          // 16 (ty, m-dim) x 32 (tx, n-dim)
#define XS_STRIDE 132         // 128 + 4 pad
#define WS_STRIDE 260         // 256 + 4 pad

// Edge-index dtype flag: 1 if edge buffer is int64, 0 if int32.
__device__ int g_edge_is_i64;

// JAX under default x64-disabled silently downcasts int64 -> int32. Detect which
// layout we actually got: for int64 values < 2^31 every odd 32-bit word is 0.
__global__ void detect_edge_dtype(const unsigned int* __restrict__ ew) {
    if (threadIdx.x == 0 && blockIdx.x == 0) {
        int is64 = 1;
        #pragma unroll 8
        for (int i = 0; i < 256; i++)
            if (ew[2 * i + 1] != 0u) { is64 = 0; break; }
        g_edge_is_i64 = is64;
    }
}

// mish(x) = x * tanh(softplus(x)) = x * (p^2-1)/(p^2+1),  p = 1 + e^x  (exact identity)
__device__ __forceinline__ float mish_f(float v) {
    float ev = __expf(fminf(v, 15.0f));   // for v>15 result == v in fp32
    float p  = 1.0f + ev;
    float p2 = p * p;
    return v * __fdividef(p2 - 1.0f, p2 + 1.0f);
}

__global__ void __launch_bounds__(NTHREADS, 1)
edge_decoder_kernel(const float* __restrict__ z,
                    const void* __restrict__ edge_raw,
                    const float* __restrict__ W1,
                    const float* __restrict__ b1,
                    const float* __restrict__ W2,
                    const float* __restrict__ b2,
                    float* __restrict__ out,
                    int n_edges)
{
    extern __shared__ float smem[];
    float* W1s = smem;                          // [D_IN_][WS_STRIDE]  k-major W1
    float* xs  = W1s + D_IN_ * WS_STRIDE;       // [D_IN_][XS_STRIDE]  k-major x tile
    float* b1s = xs  + D_IN_ * XS_STRIDE;       // [256]
    float* w2s = b1s + D_HID_;                  // [256]

    const int tid = threadIdx.x;
    const int tx  = tid & 31;   // n-dim lanes
    const int ty  = tid >> 5;   // m-dim warps

    const int is64 = g_edge_is_i64;
    const long long* e64 = (const long long*)edge_raw;
    const int*       e32 = (const int*)edge_raw;

    // ---- one-time: W1 [256][128] row-major -> k-major SMEM ----
    for (int f = tid; f < D_HID_ * (D_IN_ / 4); f += NTHREADS) {
        int h  = f >> 5;
        int k4 = (f & 31) << 2;
        float4 v = reinterpret_cast<const float4*>(W1)[f];
        W1s[(k4 + 0) * WS_STRIDE + h] = v.x;
        W1s[(k4 + 1) * WS_STRIDE + h] = v.y;
        W1s[(k4 + 2) * WS_STRIDE + h] = v.z;
        W1s[(k4 + 3) * WS_STRIDE + h] = v.w;
    }
    if (tid < D_HID_) { b1s[tid] = b1[tid]; w2s[tid] = W2[tid]; }
    const float bias2 = b2[0];
    __syncthreads();

    const int n_tiles = (n_edges + TILE_M - 1) / TILE_M;
    for (int tile = blockIdx.x; tile < n_tiles; tile += gridDim.x) {
        const int e_base = tile * TILE_M;

        // ---- gather + elementwise product into xs (k-major): 4 threads/edge ----
        {
            const int m    = tid >> 2;
            const int part = tid & 3;
            const int e    = e_base + m;
            if (e < n_edges) {
                long long i0, i1;
                if (is64) { i0 = e64[e]; i1 = e64[n_edges + e]; }
                else      { i0 = e32[e]; i1 = e32[n_edges + e]; }
                const float4* z0 = reinterpret_cast<const float4*>(z) + i0 * (D_IN_ / 4);
                const float4* z1 = reinterpret_cast<const float4*>(z) + i1 * (D_IN_ / 4);
                #pragma unroll
                for (int q = 0; q < 8; q++) {
                    int k4 = part * 8 + q;
                    float4 a = z0[k4];
                    float4 b = z1[k4];
                    int k = k4 * 4;
                    xs[(k + 0) * XS_STRIDE + m] = a.x * b.x;
                    xs[(k + 1) * XS_STRIDE + m] = a.y * b.y;
                    xs[(k + 2) * XS_STRIDE + m] = a.z * b.z;
                    xs[(k + 3) * XS_STRIDE + m] = a.w * b.w;
                }
            } else {
                #pragma unroll
                for (int q = 0; q < 8; q++) {
                    int k = (part * 8 + q) * 4;
                    xs[(k + 0) * XS_STRIDE + m] = 0.0f;
                    xs[(k + 1) * XS_STRIDE + m] = 0.0f;
                    xs[(k + 2) * XS_STRIDE + m] = 0.0f;
                    xs[(k + 3) * XS_STRIDE + m] = 0.0f;
                }
            }
        }
        __syncthreads();

        // ---- GEMM: 8(m) x 8(n) register tile per thread ----
        float acc[8][8];
        #pragma unroll
        for (int i = 0; i < 8; i++)
            #pragma unroll
            for (int j = 0; j < 8; j++) acc[i][j] = 0.0f;

        #pragma unroll 4
        for (int k = 0; k < D_IN_; k++) {
            float4 a0 = *reinterpret_cast<const float4*>(&xs [k * XS_STRIDE + ty * 4]);
            float4 a1 = *reinterpret_cast<const float4*>(&xs [k * XS_STRIDE + 64 + ty * 4]);
            float4 c0 = *reinterpret_cast<const float4*>(&W1s[k * WS_STRIDE + tx * 4]);
            float4 c1 = *reinterpret_cast<const float4*>(&W1s[k * WS_STRIDE + 128 + tx * 4]);
            float av[8] = {a0.x, a0.y, a0.z, a0.w, a1.x, a1.y, a1.z, a1.w};
            float bv[8] = {c0.x, c0.y, c0.z, c0.w, c1.x, c1.y, c1.z, c1.w};
            #pragma unroll
            for (int i = 0; i < 8; i++)
                #pragma unroll
                for (int j = 0; j < 8; j++)
                    acc[i][j] = fmaf(av[i], bv[j], acc[i][j]);
        }

        // ---- epilogue: mish, W2-weighted sum, warp-reduce over tx ----
        float psum[8];
        #pragma unroll
        for (int i = 0; i < 8; i++) psum[i] = 0.0f;

        #pragma unroll
        for (int j = 0; j < 8; j++) {
            int n = (j < 4) ? (tx * 4 + j) : (128 + tx * 4 + (j - 4));
            float bb = b1s[n];
            float w  = w2s[n];
            #pragma unroll
            for (int i = 0; i < 8; i++)
                psum[i] = fmaf(w, mish_f(acc[i][j] + bb), psum[i]);
        }
        #pragma unroll
        for (int i = 0; i < 8; i++) {
            float s = psum[i];
            #pragma unroll
            for (int off = 16; off > 0; off >>= 1)
                s += __shfl_xor_sync(0xffffffffu, s, off);
            psum[i] = s;
        }
        if (tx == 0) {
            #pragma unroll
            for (int i = 0; i < 8; i++) {
                int m = (i < 4) ? (ty * 4 + i) : (64 + ty * 4 + (i - 4));
                int e = e_base + m;
                if (e < n_edges) {
                    float v = psum[i] + bias2;
                    out[e] = __fdividef(1.0f, 1.0f + __expf(-v));
                }
            }
        }
        __syncthreads();
    }
}

extern "C" void kernel_launch(void* const* d_in, const int* in_sizes, int n_in,
                              void* d_out, int out_size) {
    const float* zp  = (const float*)d_in[0];
    const void*  ep  = d_in[1];
    const float* W1p = (const float*)d_in[2];
    const float* b1p = (const float*)d_in[3];
    const float* W2p = (const float*)d_in[4];
    const float* b2p = (const float*)d_in[5];
    float* outp = (float*)d_out;
    const int n_edges = out_size;   // [E, 1] fp32

    const size_t smem_bytes =
        (size_t)(D_IN_ * WS_STRIDE + D_IN_ * XS_STRIDE + 2 * D_HID_) * sizeof(float);
    cudaFuncSetAttribute(edge_decoder_kernel,
                         cudaFuncAttributeMaxDynamicSharedMemorySize, (int)smem_bytes);

    int sms = 148;
    cudaDeviceGetAttribute(&sms, cudaDevAttrMultiProcessorCount, 0);

    detect_edge_dtype<<<1, 32>>>((const unsigned int*)ep);
    edge_decoder_kernel<<<sms, NTHREADS, smem_bytes>>>(
        zp, ep, W1p, b1p, W2p, b2p, outp, n_edges);
}

// round 6
// speedup vs baseline: 1.8078x; 1.8078x over previous
#include <cuda_runtime.h>
#include <cuda_fp16.h>
#include <cstdint>

#define D_IN_    128
#define D_HID_   256
#define TILE_M   128
#define NTHREADS 512

// ---- SMEM byte layout (row stride 256B = 128 fp16; 16B-chunk XOR swizzle) ----
#define A_HI_OFF   0         // 128 x 128 fp16 = 32 KB
#define A_LO_OFF   32768
#define W_HI_OFF   65536     // 256 x 128 fp16 = 64 KB
#define W_LO_OFF   131072
#define BW_OFF     196608    // float2[256] {b1, w2} = 2 KB
#define PART_OFF   198656    // float[128][4] = 2 KB
#define SMEM_TOTAL 200704

__device__ int g_edge_is_i64;

__global__ void detect_edge_dtype(const unsigned int* __restrict__ ew) {
    if (threadIdx.x == 0 && blockIdx.x == 0) {
        int is64 = 1;
        for (int i = 0; i < 256; i++)
            if (ew[2 * i + 1] != 0u) { is64 = 0; break; }
        g_edge_is_i64 = is64;
    }
}

__device__ __forceinline__ uint32_t smem_to_u32(const void* p) {
    uint32_t a;
    asm("{ .reg .u64 t; cvta.to.shared.u64 t, %1; cvt.u32.u64 %0, t; }" : "=r"(a) : "l"(p));
    return a;
}

#define LDSM_X4(r, addr) \
    asm volatile("ldmatrix.sync.aligned.m8n8.x4.shared.b16 {%0,%1,%2,%3}, [%4];" \
        : "=r"((r)[0]), "=r"((r)[1]), "=r"((r)[2]), "=r"((r)[3]) : "r"(addr))
#define LDSM_X2(r, addr) \
    asm volatile("ldmatrix.sync.aligned.m8n8.x2.shared.b16 {%0,%1}, [%2];" \
        : "=r"((r)[0]), "=r"((r)[1]) : "r"(addr))
#define MMA16816(c, a, b) \
    asm volatile("mma.sync.aligned.m16n8k16.row.col.f32.f16.f16.f32 " \
        "{%0,%1,%2,%3}, {%4,%5,%6,%7}, {%8,%9}, {%0,%1,%2,%3};" \
        : "+f"((c)[0]), "+f"((c)[1]), "+f"((c)[2]), "+f"((c)[3]) \
        : "r"((a)[0]), "r"((a)[1]), "r"((a)[2]), "r"((a)[3]), "r"((b)[0]), "r"((b)[1]))

// mish(x) = x * (p^2-1)/(p^2+1), p = 1+e^x   (exact identity)
__device__ __forceinline__ float mish_f(float v) {
    float ev = __expf(fminf(v, 15.0f));
    float p  = 1.0f + ev;
    float p2 = p * p;
    return v * __fdividef(p2 - 1.0f, p2 + 1.0f);
}

// pack two floats to fp16x2 (hi), residuals out
__device__ __forceinline__ uint32_t pack_hi(float x, float y, float& rx, float& ry) {
    __half hx = __float2half_rn(x), hy = __float2half_rn(y);
    rx = x - __half2float(hx); ry = y - __half2float(hy);
    return ((uint32_t)__half_as_ushort(hy) << 16) | (uint32_t)__half_as_ushort(hx);
}
__device__ __forceinline__ uint32_t pack_lo(float rx, float ry) {
    __half lx = __float2half_rn(rx), ly = __float2half_rn(ry);
    return ((uint32_t)__half_as_ushort(ly) << 16) | (uint32_t)__half_as_ushort(lx);
}

// pack 8 products into hi/lo uint4 and store swizzled
__device__ __forceinline__ void pack8_store(char* smem_c, uint32_t hi_off, uint32_t lo_off,
                                            const float* p) {
    float r[8]; uint4 hi, lo;
    hi.x = pack_hi(p[0], p[1], r[0], r[1]);
    hi.y = pack_hi(p[2], p[3], r[2], r[3]);
    hi.z = pack_hi(p[4], p[5], r[4], r[5]);
    hi.w = pack_hi(p[6], p[7], r[6], r[7]);
    lo.x = pack_lo(r[0], r[1]); lo.y = pack_lo(r[2], r[3]);
    lo.z = pack_lo(r[4], r[5]); lo.w = pack_lo(r[6], r[7]);
    *reinterpret_cast<uint4*>(smem_c + hi_off) = hi;
    *reinterpret_cast<uint4*>(smem_c + lo_off) = lo;
}

__global__ void __launch_bounds__(NTHREADS, 1)
edge_decoder_hmma(const float* __restrict__ z,
                  const void* __restrict__ edge_raw,
                  const float* __restrict__ W1,
                  const float* __restrict__ b1,
                  const float* __restrict__ W2,
                  const float* __restrict__ b2,
                  float* __restrict__ out,
                  int n_edges)
{
    extern __shared__ char smem[];
    const uint32_t sbase = smem_to_u32(smem);
    const int tid  = threadIdx.x;
    const int wid  = tid >> 5;
    const int lane = tid & 31;
    const int wm = (wid & 3) * 32;       // warp m-base (4 m-warps)
    const int wn = (wid >> 2) * 64;      // warp n-base (4 n-warps)

    const int is64 = g_edge_is_i64;
    const long long* e64 = (const long long*)edge_raw;
    const int*       e32 = (const int*)edge_raw;

    float2* bw2s = (float2*)(smem + BW_OFF);
    float*  part = (float*)(smem + PART_OFF);   // [128][4]

    // ---- prologue: W1 [256][128] -> fp16 hi/lo SMEM, swizzled ----
    for (int c = tid; c < D_HID_ * 16; c += NTHREADS) {
        int n = c >> 4, ch = c & 15;
        const float4* wr = reinterpret_cast<const float4*>(W1) + n * 32 + ch * 2;
        float4 v0 = wr[0], v1 = wr[1];
        float p[8] = {v0.x, v0.y, v0.z, v0.w, v1.x, v1.y, v1.z, v1.w};
        uint32_t kb = (uint32_t)ch * 16;
        uint32_t sw = (uint32_t)n * 256 + (kb ^ (((uint32_t)n & 7) << 4));
        pack8_store(smem, W_HI_OFF + sw, W_LO_OFF + sw, p);
    }
    if (tid < D_HID_) { float2 t; t.x = b1[tid]; t.y = W2[tid]; bw2s[tid] = t; }
    const float bias2 = b2[0];
    __syncthreads();

    const int n_tiles = (n_edges + TILE_M - 1) / TILE_M;
    const int grid = gridDim.x;

    // gather mapping: 4 threads/edge, 32 k each
    const int gm   = tid >> 2;
    const int gpart = tid & 3;

    for (int tile = blockIdx.x; tile < n_tiles; tile += grid) {
        const int e_base = tile * TILE_M;

        // ---- gather + product -> A hi/lo fp16, swizzled ----
        {
            const int e = e_base + gm;
            const uint32_t rb = (uint32_t)gm * 256;
            if (e < n_edges) {
                long long i0, i1;
                if (is64) { i0 = e64[e]; i1 = e64[n_edges + e]; }
                else      { i0 = e32[e]; i1 = e32[n_edges + e]; }
                const float4* z0 = reinterpret_cast<const float4*>(z) + i0 * 32 + gpart * 8;
                const float4* z1 = reinterpret_cast<const float4*>(z) + i1 * 32 + gpart * 8;
                #pragma unroll
                for (int q = 0; q < 4; q++) {
                    float4 a0 = z0[q * 2], a1 = z0[q * 2 + 1];
                    float4 c0 = z1[q * 2], c1 = z1[q * 2 + 1];
                    float p[8] = {a0.x * c0.x, a0.y * c0.y, a0.z * c0.z, a0.w * c0.w,
                                  a1.x * c1.x, a1.y * c1.y, a1.z * c1.z, a1.w * c1.w};
                    uint32_t kb = (uint32_t)(gpart * 64 + q * 16);
                    uint32_t sw = rb + (kb ^ (((uint32_t)gm & 7) << 4));
                    pack8_store(smem, A_HI_OFF + sw, A_LO_OFF + sw, p);
                }
            } else {
                uint4 zz = {0, 0, 0, 0};
                #pragma unroll
                for (int q = 0; q < 4; q++) {
                    uint32_t kb = (uint32_t)(gpart * 64 + q * 16);
                    uint32_t sw = rb + (kb ^ (((uint32_t)gm & 7) << 4));
                    *reinterpret_cast<uint4*>(smem + A_HI_OFF + sw) = zz;
                    *reinterpret_cast<uint4*>(smem + A_LO_OFF + sw) = zz;
                }
            }
        }
        __syncthreads();

        // ---- HMMA mainloop: warp tile 32(m) x 64(n), K=128 ----
        float C[2][8][4];
        #pragma unroll
        for (int mb = 0; mb < 2; mb++)
            #pragma unroll
            for (int n8 = 0; n8 < 8; n8++)
                #pragma unroll
                for (int q = 0; q < 4; q++) C[mb][n8][q] = 0.0f;

        {
            const int arow = wm + (lane & 15);
            const int bl = lane & 15;
            const int brow = wn + (bl & 7);
            #pragma unroll
            for (int k16 = 0; k16 < 8; k16++) {
                uint32_t Ahi[2][4], Alo[2][4];
                uint32_t akb = (uint32_t)(k16 * 32 + (lane >> 4) * 16);
                uint32_t ad = sbase + A_HI_OFF + (uint32_t)arow * 256
                            + (akb ^ (((uint32_t)arow & 7) << 4));
                LDSM_X4(Ahi[0], ad);
                LDSM_X4(Ahi[1], ad + 16 * 256);
                LDSM_X4(Alo[0], ad + (A_LO_OFF - A_HI_OFF));
                LDSM_X4(Alo[1], ad + (A_LO_OFF - A_HI_OFF) + 16 * 256);

                uint32_t bkb = (uint32_t)(k16 * 32 + ((bl >> 3) & 1) * 16);
                uint32_t bd = sbase + W_HI_OFF + (uint32_t)brow * 256
                            + (bkb ^ (((uint32_t)brow & 7) << 4));
                #pragma unroll
                for (int n8 = 0; n8 < 8; n8++) {
                    uint32_t Bhi[2], Blo[2];
                    LDSM_X2(Bhi, bd + (uint32_t)n8 * 2048);
                    LDSM_X2(Blo, bd + (uint32_t)n8 * 2048 + (W_LO_OFF - W_HI_OFF));
                    #pragma unroll
                    for (int mb = 0; mb < 2; mb++) {
                        MMA16816(C[mb][n8], Ahi[mb], Bhi);
                        MMA16816(C[mb][n8], Alo[mb], Bhi);
                        MMA16816(C[mb][n8], Ahi[mb], Blo);
                    }
                }
            }
        }

        // ---- epilogue: mish + W2-weighted reduce, in registers ----
        {
            float psum[4] = {0.f, 0.f, 0.f, 0.f};   // [mb*2 + half]
            #pragma unroll
            for (int n8 = 0; n8 < 8; n8++) {
                const int n = wn + n8 * 8 + 2 * (lane & 3);
                float2 bw0 = bw2s[n];
                float2 bw1 = bw2s[n + 1];
                #pragma unroll
                for (int mb = 0; mb < 2; mb++) {
                    const float* c = C[mb][n8];
                    psum[mb * 2 + 0] = fmaf(bw0.y, mish_f(c[0] + bw0.x),
                                       fmaf(bw1.y, mish_f(c[1] + bw1.x), psum[mb * 2 + 0]));
                    psum[mb * 2 + 1] = fmaf(bw0.y, mish_f(c[2] + bw0.x),
                                       fmaf(bw1.y, mish_f(c[3] + bw1.x), psum[mb * 2 + 1]));
                }
            }
            // reduce over lane%4 (disjoint n slices)
            #pragma unroll
            for (int q = 0; q < 4; q++) {
                psum[q] += __shfl_xor_sync(0xffffffffu, psum[q], 1);
                psum[q] += __shfl_xor_sync(0xffffffffu, psum[q], 2);
            }
            if ((lane & 3) == 0) {
                const int r = lane >> 2;   // 0..7
                const int wcol = wid >> 2;
                #pragma unroll
                for (int mb = 0; mb < 2; mb++) {
                    part[(wm + mb * 16 + r) * 4 + wcol]     = psum[mb * 2 + 0];
                    part[(wm + mb * 16 + r + 8) * 4 + wcol] = psum[mb * 2 + 1];
                }
            }
        }
        __syncthreads();

        if (tid < TILE_M) {
            const int e = e_base + tid;
            if (e < n_edges) {
                float s = (part[tid * 4 + 0] + part[tid * 4 + 1])
                        + (part[tid * 4 + 2] + part[tid * 4 + 3]) + bias2;
                out[e] = __fdividef(1.0f, 1.0f + __expf(-s));
            }
        }
        // no extra sync needed: next gather writes A (read only before the
        // barrier above); part is rewritten only after the next __syncthreads.
    }
}

extern "C" void kernel_launch(void* const* d_in, const int* in_sizes, int n_in,
                              void* d_out, int out_size) {
    const float* zp  = (const float*)d_in[0];
    const void*  ep  = d_in[1];
    const float* W1p = (const float*)d_in[2];
    const float* b1p = (const float*)d_in[3];
    const float* W2p = (const float*)d_in[4];
    const float* b2p = (const float*)d_in[5];
    float* outp = (float*)d_out;
    const int n_edges = out_size;

    cudaFuncSetAttribute(edge_decoder_hmma,
                         cudaFuncAttributeMaxDynamicSharedMemorySize, SMEM_TOTAL);
    int sms = 148;
    cudaDeviceGetAttribute(&sms, cudaDevAttrMultiProcessorCount, 0);

    detect_edge_dtype<<<1, 32>>>((const unsigned int*)ep);
    edge_decoder_hmma<<<sms, NTHREADS, SMEM_TOTAL>>>(
        zp, ep, W1p, b1p, W2p, b2p, outp, n_edges);
}

// round 7
// speedup vs baseline: 2.1717x; 1.2013x over previous
#include <cuda_runtime.h>
#include <cuda_fp16.h>
#include <cstdint>

#define D_IN_    128
#define D_HID_   256
#define TILE_M   64
#define NTHREADS 256

// ---- SMEM byte layout per CTA (row stride 256B = 128 fp16; 16B-chunk XOR swizzle) ----
#define A_HI_OFF   0         // 64 x 128 fp16 = 16 KB
#define A_LO_OFF   16384
#define W_HI_OFF   32768     // 256 x 128 fp16 = 64 KB
#define BW_OFF     98304     // float2[256] {b1, w2} = 2 KB
#define PART_OFF   100352    // float[64][4] = 1 KB
#define SMEM_TOTAL 101376

__device__ int g_edge_is_i64;

__global__ void detect_edge_dtype(const unsigned int* __restrict__ ew) {
    if (threadIdx.x == 0 && blockIdx.x == 0) {
        int is64 = 1;
        for (int i = 0; i < 256; i++)
            if (ew[2 * i + 1] != 0u) { is64 = 0; break; }
        g_edge_is_i64 = is64;
    }
}

__device__ __forceinline__ uint32_t smem_to_u32(const void* p) {
    uint32_t a;
    asm("{ .reg .u64 t; cvta.to.shared.u64 t, %1; cvt.u32.u64 %0, t; }" : "=r"(a) : "l"(p));
    return a;
}

#define LDSM_X4(r, addr) \
    asm volatile("ldmatrix.sync.aligned.m8n8.x4.shared.b16 {%0,%1,%2,%3}, [%4];" \
        : "=r"((r)[0]), "=r"((r)[1]), "=r"((r)[2]), "=r"((r)[3]) : "r"(addr))
#define LDSM_X2(r, addr) \
    asm volatile("ldmatrix.sync.aligned.m8n8.x2.shared.b16 {%0,%1}, [%2];" \
        : "=r"((r)[0]), "=r"((r)[1]) : "r"(addr))
#define MMA16816(c, a, b) \
    asm volatile("mma.sync.aligned.m16n8k16.row.col.f32.f16.f16.f32 " \
        "{%0,%1,%2,%3}, {%4,%5,%6,%7}, {%8,%9}, {%0,%1,%2,%3};" \
        : "+f"((c)[0]), "+f"((c)[1]), "+f"((c)[2]), "+f"((c)[3]) \
        : "r"((a)[0]), "r"((a)[1]), "r"((a)[2]), "r"((a)[3]), "r"((b)[0]), "r"((b)[1]))

// mish(x) = x * (p^2-1)/(p^2+1), p = 1+e^x   (exact identity)
__device__ __forceinline__ float mish_f(float v) {
    float ev = __expf(fminf(v, 15.0f));
    float p  = 1.0f + ev;
    float p2 = p * p;
    return v * __fdividef(p2 - 1.0f, p2 + 1.0f);
}

__device__ __forceinline__ uint32_t pack_hi(float x, float y, float& rx, float& ry) {
    __half hx = __float2half_rn(x), hy = __float2half_rn(y);
    rx = x - __half2float(hx); ry = y - __half2float(hy);
    return ((uint32_t)__half_as_ushort(hy) << 16) | (uint32_t)__half_as_ushort(hx);
}
__device__ __forceinline__ uint32_t pack_lo(float rx, float ry) {
    __half lx = __float2half_rn(rx), ly = __float2half_rn(ry);
    return ((uint32_t)__half_as_ushort(ly) << 16) | (uint32_t)__half_as_ushort(lx);
}
__device__ __forceinline__ uint32_t pack2(float x, float y) {
    __half hx = __float2half_rn(x), hy = __float2half_rn(y);
    return ((uint32_t)__half_as_ushort(hy) << 16) | (uint32_t)__half_as_ushort(hx);
}

// pack 8 products into hi/lo uint4 and store swizzled (A path)
__device__ __forceinline__ void pack8_store_hilo(char* smem_c, uint32_t hi_off, uint32_t lo_off,
                                                 const float* p) {
    float r[8]; uint4 hi, lo;
    hi.x = pack_hi(p[0], p[1], r[0], r[1]);
    hi.y = pack_hi(p[2], p[3], r[2], r[3]);
    hi.z = pack_hi(p[4], p[5], r[4], r[5]);
    hi.w = pack_hi(p[6], p[7], r[6], r[7]);
    lo.x = pack_lo(r[0], r[1]); lo.y = pack_lo(r[2], r[3]);
    lo.z = pack_lo(r[4], r[5]); lo.w = pack_lo(r[6], r[7]);
    *reinterpret_cast<uint4*>(smem_c + hi_off) = hi;
    *reinterpret_cast<uint4*>(smem_c + lo_off) = lo;
}

__global__ void __launch_bounds__(NTHREADS, 2)
edge_decoder_hmma(const float* __restrict__ z,
                  const void* __restrict__ edge_raw,
                  const float* __restrict__ W1,
                  const float* __restrict__ b1,
                  const float* __restrict__ W2,
                  const float* __restrict__ b2,
                  float* __restrict__ out,
                  int n_edges)
{
    extern __shared__ char smem[];
    const uint32_t sbase = smem_to_u32(smem);
    const int tid  = threadIdx.x;
    const int wid  = tid >> 5;
    const int lane = tid & 31;
    const int wm = (wid & 1) * 32;       // 2 m-warps x 32 rows
    const int wn = (wid >> 1) * 64;      // 4 n-warps x 64 cols

    const int is64 = g_edge_is_i64;
    const long long* e64 = (const long long*)edge_raw;
    const int*       e32 = (const int*)edge_raw;

    float2* bw2s = (float2*)(smem + BW_OFF);
    float*  part = (float*)(smem + PART_OFF);   // [64][4]

    // ---- prologue: W1 [256][128] -> fp16 hi SMEM, swizzled ----
    for (int c = tid; c < D_HID_ * 16; c += NTHREADS) {
        int n = c >> 4, ch = c & 15;
        const float4* wr = reinterpret_cast<const float4*>(W1) + n * 32 + ch * 2;
        float4 v0 = wr[0], v1 = wr[1];
        uint4 hi;
        hi.x = pack2(v0.x, v0.y); hi.y = pack2(v0.z, v0.w);
        hi.z = pack2(v1.x, v1.y); hi.w = pack2(v1.z, v1.w);
        uint32_t kb = (uint32_t)ch * 16;
        uint32_t sw = (uint32_t)n * 256 + (kb ^ (((uint32_t)n & 7) << 4));
        *reinterpret_cast<uint4*>(smem + W_HI_OFF + sw) = hi;
    }
    if (tid < D_HID_) { float2 t; t.x = b1[tid]; t.y = W2[tid]; bw2s[tid] = t; }
    const float bias2 = b2[0];
    __syncthreads();

    const int n_tiles = (n_edges + TILE_M - 1) / TILE_M;
    const int grid = gridDim.x;

    // gather mapping: 4 threads/edge, 32 k-dims each
    const int gm    = tid >> 2;   // 0..63
    const int gpart = tid & 3;

    for (int tile = blockIdx.x; tile < n_tiles; tile += grid) {
        const int e_base = tile * TILE_M;

        // ---- gather + product -> A hi/lo fp16, swizzled ----
        {
            const int e = e_base + gm;
            const uint32_t rb = (uint32_t)gm * 256;
            if (e < n_edges) {
                long long i0, i1;
                if (is64) { i0 = e64[e]; i1 = e64[n_edges + e]; }
                else      { i0 = e32[e]; i1 = e32[n_edges + e]; }
                const float4* z0 = reinterpret_cast<const float4*>(z) + i0 * 32 + gpart * 8;
                const float4* z1 = reinterpret_cast<const float4*>(z) + i1 * 32 + gpart * 8;
                #pragma unroll
                for (int q = 0; q < 4; q++) {
                    float4 a0 = z0[q * 2], a1 = z0[q * 2 + 1];
                    float4 c0 = z1[q * 2], c1 = z1[q * 2 + 1];
                    float p[8] = {a0.x * c0.x, a0.y * c0.y, a0.z * c0.z, a0.w * c0.w,
                                  a1.x * c1.x, a1.y * c1.y, a1.z * c1.z, a1.w * c1.w};
                    uint32_t kb = (uint32_t)(gpart * 64 + q * 16);
                    uint32_t sw = rb + (kb ^ (((uint32_t)gm & 7) << 4));
                    pack8_store_hilo(smem, A_HI_OFF + sw, A_LO_OFF + sw, p);
                }
            } else {
                uint4 zz = {0, 0, 0, 0};
                #pragma unroll
                for (int q = 0; q < 4; q++) {
                    uint32_t kb = (uint32_t)(gpart * 64 + q * 16);
                    uint32_t sw = rb + (kb ^ (((uint32_t)gm & 7) << 4));
                    *reinterpret_cast<uint4*>(smem + A_HI_OFF + sw) = zz;
                    *reinterpret_cast<uint4*>(smem + A_LO_OFF + sw) = zz;
                }
            }
        }
        __syncthreads();

        // ---- HMMA mainloop: warp tile 32(m) x 64(n), K=128, 2-term split ----
        float C[2][8][4];
        #pragma unroll
        for (int mb = 0; mb < 2; mb++)
            #pragma unroll
            for (int n8 = 0; n8 < 8; n8++)
                #pragma unroll
                for (int q = 0; q < 4; q++) C[mb][n8][q] = 0.0f;

        {
            const int arow = wm + (lane & 15);
            const int bl = lane & 15;
            const int brow = wn + (bl & 7);
            #pragma unroll
            for (int k16 = 0; k16 < 8; k16++) {
                uint32_t Ahi[2][4], Alo[2][4];
                uint32_t akb = (uint32_t)(k16 * 32 + (lane >> 4) * 16);
                uint32_t ad = sbase + A_HI_OFF + (uint32_t)arow * 256
                            + (akb ^ (((uint32_t)arow & 7) << 4));
                LDSM_X4(Ahi[0], ad);
                LDSM_X4(Ahi[1], ad + 16 * 256);
                LDSM_X4(Alo[0], ad + (A_LO_OFF - A_HI_OFF));
                LDSM_X4(Alo[1], ad + (A_LO_OFF - A_HI_OFF) + 16 * 256);

                uint32_t bkb = (uint32_t)(k16 * 32 + ((bl >> 3) & 1) * 16);
                uint32_t bd = sbase + W_HI_OFF + (uint32_t)brow * 256
                            + (bkb ^ (((uint32_t)brow & 7) << 4));
                #pragma unroll
                for (int n8 = 0; n8 < 8; n8++) {
                    uint32_t Bhi[2];
                    LDSM_X2(Bhi, bd + (uint32_t)n8 * 2048);
                    #pragma unroll
                    for (int mb = 0; mb < 2; mb++) {
                        MMA16816(C[mb][n8], Ahi[mb], Bhi);
                        MMA16816(C[mb][n8], Alo[mb], Bhi);
                    }
                }
            }
        }

        // ---- epilogue: mish + W2-weighted reduce, in registers ----
        {
            float psum[4] = {0.f, 0.f, 0.f, 0.f};   // [mb*2 + half]
            #pragma unroll
            for (int n8 = 0; n8 < 8; n8++) {
                const int n = wn + n8 * 8 + 2 * (lane & 3);
                float2 bw0 = bw2s[n];
                float2 bw1 = bw2s[n + 1];
                #pragma unroll
                for (int mb = 0; mb < 2; mb++) {
                    const float* c = C[mb][n8];
                    psum[mb * 2 + 0] = fmaf(bw0.y, mish_f(c[0] + bw0.x),
                                       fmaf(bw1.y, mish_f(c[1] + bw1.x), psum[mb * 2 + 0]));
                    psum[mb * 2 + 1] = fmaf(bw0.y, mish_f(c[2] + bw0.x),
                                       fmaf(bw1.y, mish_f(c[3] + bw1.x), psum[mb * 2 + 1]));
                }
            }
            #pragma unroll
            for (int q = 0; q < 4; q++) {
                psum[q] += __shfl_xor_sync(0xffffffffu, psum[q], 1);
                psum[q] += __shfl_xor_sync(0xffffffffu, psum[q], 2);
            }
            if ((lane & 3) == 0) {
                const int r = lane >> 2;   // 0..7
                const int wcol = wid >> 1; // 0..3
                #pragma unroll
                for (int mb = 0; mb < 2; mb++) {
                    part[(wm + mb * 16 + r) * 4 + wcol]     = psum[mb * 2 + 0];
                    part[(wm + mb * 16 + r + 8) * 4 + wcol] = psum[mb * 2 + 1];
                }
            }
        }
        __syncthreads();

        if (tid < TILE_M) {
            const int e = e_base + tid;
            if (e < n_edges) {
                float s = (part[tid * 4 + 0] + part[tid * 4 + 1])
                        + (part[tid * 4 + 2] + part[tid * 4 + 3]) + bias2;
                out[e] = __fdividef(1.0f, 1.0f + __expf(-s));
            }
        }
        // next gather writes A only; part rewritten only after next barrier
    }
}

extern "C" void kernel_launch(void* const* d_in, const int* in_sizes, int n_in,
                              void* d_out, int out_size) {
    const float* zp  = (const float*)d_in[0];
    const void*  ep  = d_in[1];
    const float* W1p = (const float*)d_in[2];
    const float* b1p = (const float*)d_in[3];
    const float* W2p = (const float*)d_in[4];
    const float* b2p = (const float*)d_in[5];
    float* outp = (float*)d_out;
    const int n_edges = out_size;

    cudaFuncSetAttribute(edge_decoder_hmma,
                         cudaFuncAttributeMaxDynamicSharedMemorySize, SMEM_TOTAL);
    int sms = 148;
    cudaDeviceGetAttribute(&sms, cudaDevAttrMultiProcessorCount, 0);

    detect_edge_dtype<<<1, 32>>>((const unsigned int*)ep);
    edge_decoder_hmma<<<sms * 2, NTHREADS, SMEM_TOTAL>>>(
        zp, ep, W1p, b1p, W2p, b2p, outp, n_edges);
}

// round 8
// speedup vs baseline: 3.6632x; 1.6868x over previous
#include <cuda_runtime.h>
#include <cuda_fp16.h>
#include <cstdint>

#define D_IN_    128
#define D_HID_   256
#define TILE_M   64
#define NTHREADS 256

// ---- SMEM byte layout per CTA (row stride 256B = 128 fp16; 16B-chunk XOR swizzle) ----
#define A_HI_OFF   0         // 64 x 128 fp16 = 16 KB
#define W_HI_OFF   16384     // 256 x 128 fp16 = 64 KB
#define BW_OFF     81920     // float2[256] {b1, w2} = 2 KB
#define PART_OFF   83968     // float[64][4] = 1 KB
#define SMEM_TOTAL 84992

__device__ int g_edge_is_i64;

__global__ void detect_edge_dtype(const unsigned int* __restrict__ ew) {
    if (threadIdx.x == 0 && blockIdx.x == 0) {
        int is64 = 1;
        for (int i = 0; i < 256; i++)
            if (ew[2 * i + 1] != 0u) { is64 = 0; break; }
        g_edge_is_i64 = is64;
    }
}

__device__ __forceinline__ uint32_t smem_to_u32(const void* p) {
    uint32_t a;
    asm("{ .reg .u64 t; cvta.to.shared.u64 t, %1; cvt.u32.u64 %0, t; }" : "=r"(a) : "l"(p));
    return a;
}

#define LDSM_X4(r, addr) \
    asm volatile("ldmatrix.sync.aligned.m8n8.x4.shared.b16 {%0,%1,%2,%3}, [%4];" \
        : "=r"((r)[0]), "=r"((r)[1]), "=r"((r)[2]), "=r"((r)[3]) : "r"(addr))
#define LDSM_X2(r, addr) \
    asm volatile("ldmatrix.sync.aligned.m8n8.x2.shared.b16 {%0,%1}, [%2];" \
        : "=r"((r)[0]), "=r"((r)[1]) : "r"(addr))
#define MMA16816(c, a, b) \
    asm volatile("mma.sync.aligned.m16n8k16.row.col.f32.f16.f16.f32 " \
        "{%0,%1,%2,%3}, {%4,%5,%6,%7}, {%8,%9}, {%0,%1,%2,%3};" \
        : "+f"((c)[0]), "+f"((c)[1]), "+f"((c)[2]), "+f"((c)[3]) \
        : "r"((a)[0]), "r"((a)[1]), "r"((a)[2]), "r"((a)[3]), "r"((b)[0]), "r"((b)[1]))

// mish(x) = x * (p^2-1)/(p^2+1), p = 1+e^x   (exact identity)
__device__ __forceinline__ float mish_f(float v) {
    float ev = __expf(fminf(v, 15.0f));
    float p  = 1.0f + ev;
    float p2 = p * p;
    return v * __fdividef(p2 - 1.0f, p2 + 1.0f);
}

__device__ __forceinline__ uint32_t pack2(float x, float y) {
    __half hx = __float2half_rn(x), hy = __float2half_rn(y);
    return ((uint32_t)__half_as_ushort(hy) << 16) | (uint32_t)__half_as_ushort(hx);
}

__global__ void __launch_bounds__(NTHREADS, 2)
edge_decoder_hmma(const float* __restrict__ z,
                  const void* __restrict__ edge_raw,
                  const float* __restrict__ W1,
                  const float* __restrict__ b1,
                  const float* __restrict__ W2,
                  const float* __restrict__ b2,
                  float* __restrict__ out,
                  int n_edges)
{
    extern __shared__ char smem[];
    const uint32_t sbase = smem_to_u32(smem);
    const int tid  = threadIdx.x;
    const int wid  = tid >> 5;
    const int lane = tid & 31;
    const int wm = (wid & 1) * 32;       // 2 m-warps x 32 rows
    const int wn = (wid >> 1) * 64;      // 4 n-warps x 64 cols

    const int is64 = g_edge_is_i64;
    const long long* e64 = (const long long*)edge_raw;
    const int*       e32 = (const int*)edge_raw;

    float2* bw2s = (float2*)(smem + BW_OFF);
    float*  part = (float*)(smem + PART_OFF);   // [64][4]

    // ---- prologue: W1 [256][128] -> fp16 SMEM, swizzled ----
    for (int c = tid; c < D_HID_ * 16; c += NTHREADS) {
        int n = c >> 4, ch = c & 15;
        const float4* wr = reinterpret_cast<const float4*>(W1) + n * 32 + ch * 2;
        float4 v0 = wr[0], v1 = wr[1];
        uint4 hi;
        hi.x = pack2(v0.x, v0.y); hi.y = pack2(v0.z, v0.w);
        hi.z = pack2(v1.x, v1.y); hi.w = pack2(v1.z, v1.w);
        uint32_t kb = (uint32_t)ch * 16;
        uint32_t sw = (uint32_t)n * 256 + (kb ^ (((uint32_t)n & 7) << 4));
        *reinterpret_cast<uint4*>(smem + W_HI_OFF + sw) = hi;
    }
    if (tid < D_HID_) { float2 t; t.x = b1[tid]; t.y = W2[tid]; bw2s[tid] = t; }
    const float bias2 = b2[0];
    __syncthreads();

    const int n_tiles = (n_edges + TILE_M - 1) / TILE_M;
    const int grid = gridDim.x;

    // gather mapping: 4 threads/edge, 32 k-dims each
    const int gm    = tid >> 2;   // 0..63
    const int gpart = tid & 3;

    for (int tile = blockIdx.x; tile < n_tiles; tile += grid) {
        const int e_base = tile * TILE_M;

        // ---- gather + product -> A fp16, swizzled ----
        {
            const int e = e_base + gm;
            const uint32_t rb = (uint32_t)gm * 256;
            if (e < n_edges) {
                long long i0, i1;
                if (is64) { i0 = e64[e]; i1 = e64[n_edges + e]; }
                else      { i0 = e32[e]; i1 = e32[n_edges + e]; }
                const float4* z0 = reinterpret_cast<const float4*>(z) + i0 * 32 + gpart * 8;
                const float4* z1 = reinterpret_cast<const float4*>(z) + i1 * 32 + gpart * 8;
                #pragma unroll
                for (int q = 0; q < 4; q++) {
                    float4 a0 = z0[q * 2], a1 = z0[q * 2 + 1];
                    float4 c0 = z1[q * 2], c1 = z1[q * 2 + 1];
                    uint4 hi;
                    hi.x = pack2(a0.x * c0.x, a0.y * c0.y);
                    hi.y = pack2(a0.z * c0.z, a0.w * c0.w);
                    hi.z = pack2(a1.x * c1.x, a1.y * c1.y);
                    hi.w = pack2(a1.z * c1.z, a1.w * c1.w);
                    uint32_t kb = (uint32_t)(gpart * 64 + q * 16);
                    uint32_t sw = rb + (kb ^ (((uint32_t)gm & 7) << 4));
                    *reinterpret_cast<uint4*>(smem + A_HI_OFF + sw) = hi;
                }
            } else {
                uint4 zz = {0, 0, 0, 0};
                #pragma unroll
                for (int q = 0; q < 4; q++) {
                    uint32_t kb = (uint32_t)(gpart * 64 + q * 16);
                    uint32_t sw = rb + (kb ^ (((uint32_t)gm & 7) << 4));
                    *reinterpret_cast<uint4*>(smem + A_HI_OFF + sw) = zz;
                }
            }
        }
        __syncthreads();

        // ---- HMMA mainloop: warp tile 32(m) x 64(n), K=128, single fp16 term ----
        float C[2][8][4];
        #pragma unroll
        for (int mb = 0; mb < 2; mb++)
            #pragma unroll
            for (int n8 = 0; n8 < 8; n8++)
                #pragma unroll
                for (int q = 0; q < 4; q++) C[mb][n8][q] = 0.0f;

        {
            const int arow = wm + (lane & 15);
            const int bl = lane & 15;
            const int brow = wn + (bl & 7);
            #pragma unroll
            for (int k16 = 0; k16 < 8; k16++) {
                uint32_t Ahi[2][4];
                uint32_t akb = (uint32_t)(k16 * 32 + (lane >> 4) * 16);
                uint32_t ad = sbase + A_HI_OFF + (uint32_t)arow * 256
                            + (akb ^ (((uint32_t)arow & 7) << 4));
                LDSM_X4(Ahi[0], ad);
                LDSM_X4(Ahi[1], ad + 16 * 256);

                uint32_t bkb = (uint32_t)(k16 * 32 + ((bl >> 3) & 1) * 16);
                uint32_t bd = sbase + W_HI_OFF + (uint32_t)brow * 256
                            + (bkb ^ (((uint32_t)brow & 7) << 4));
                #pragma unroll
                for (int n8 = 0; n8 < 8; n8++) {
                    uint32_t Bhi[2];
                    LDSM_X2(Bhi, bd + (uint32_t)n8 * 2048);
                    MMA16816(C[0][n8], Ahi[0], Bhi);
                    MMA16816(C[1][n8], Ahi[1], Bhi);
                }
            }
        }

        // ---- epilogue: mish + W2-weighted reduce, in registers ----
        {
            float psum[4] = {0.f, 0.f, 0.f, 0.f};   // [mb*2 + half]
            #pragma unroll
            for (int n8 = 0; n8 < 8; n8++) {
                const int n = wn + n8 * 8 + 2 * (lane & 3);
                float2 bw0 = bw2s[n];
                float2 bw1 = bw2s[n + 1];
                #pragma unroll
                for (int mb = 0; mb < 2; mb++) {
                    const float* c = C[mb][n8];
                    psum[mb * 2 + 0] = fmaf(bw0.y, mish_f(c[0] + bw0.x),
                                       fmaf(bw1.y, mish_f(c[1] + bw1.x), psum[mb * 2 + 0]));
                    psum[mb * 2 + 1] = fmaf(bw0.y, mish_f(c[2] + bw0.x),
                                       fmaf(bw1.y, mish_f(c[3] + bw1.x), psum[mb * 2 + 1]));
                }
            }
            #pragma unroll
            for (int q = 0; q < 4; q++) {
                psum[q] += __shfl_xor_sync(0xffffffffu, psum[q], 1);
                psum[q] += __shfl_xor_sync(0xffffffffu, psum[q], 2);
            }
            if ((lane & 3) == 0) {
                const int r = lane >> 2;   // 0..7
                const int wcol = wid >> 1; // 0..3
                #pragma unroll
                for (int mb = 0; mb < 2; mb++) {
                    part[(wm + mb * 16 + r) * 4 + wcol]     = psum[mb * 2 + 0];
                    part[(wm + mb * 16 + r + 8) * 4 + wcol] = psum[mb * 2 + 1];
                }
            }
        }
        __syncthreads();

        if (tid < TILE_M) {
            const int e = e_base + tid;
            if (e < n_edges) {
                float s = (part[tid * 4 + 0] + part[tid * 4 + 1])
                        + (part[tid * 4 + 2] + part[tid * 4 + 3]) + bias2;
                out[e] = __fdividef(1.0f, 1.0f + __expf(-s));
            }
        }
        // next gather writes A only; part rewritten only after next barrier
    }
}

extern "C" void kernel_launch(void* const* d_in, const int* in_sizes, int n_in,
                              void* d_out, int out_size) {
    const float* zp  = (const float*)d_in[0];
    const void*  ep  = d_in[1];
    const float* W1p = (const float*)d_in[2];
    const float* b1p = (const float*)d_in[3];
    const float* W2p = (const float*)d_in[4];
    const float* b2p = (const float*)d_in[5];
    float* outp = (float*)d_out;
    const int n_edges = out_size;

    cudaFuncSetAttribute(edge_decoder_hmma,
                         cudaFuncAttributeMaxDynamicSharedMemorySize, SMEM_TOTAL);
    int sms = 148;
    cudaDeviceGetAttribute(&sms, cudaDevAttrMultiProcessorCount, 0);

    detect_edge_dtype<<<1, 32>>>((const unsigned int*)ep);
    edge_decoder_hmma<<<sms * 2, NTHREADS, SMEM_TOTAL>>>(
        zp, ep, W1p, b1p, W2p, b2p, outp, n_edges);
}

// round 9
// speedup vs baseline: 5.2886x; 1.4437x over previous
#include <cuda_runtime.h>
#include <cuda_fp16.h>
#include <cstdint>

#define D_IN_    128
#define D_HID_   256
#define TILE_M   64
#define NTHREADS 256

// ---- SMEM byte layout per CTA (row stride 256B = 128 fp16; 16B-chunk XOR swizzle) ----
#define A_HI_OFF   0         // 64 x 128 fp16 = 16 KB
#define W_HI_OFF   16384     // 256 x 128 fp16 = 64 KB
#define BW_OFF     81920     // float2[256] {b1, w2} = 2 KB
#define PART_OFF   83968     // float[64][4] = 1 KB
#define SMEM_TOTAL 84992

__device__ int g_edge_is_i64;

__global__ void detect_edge_dtype(const unsigned int* __restrict__ ew) {
    if (threadIdx.x == 0 && blockIdx.x == 0) {
        int is64 = 1;
        for (int i = 0; i < 256; i++)
            if (ew[2 * i + 1] != 0u) { is64 = 0; break; }
        g_edge_is_i64 = is64;
    }
}

__device__ __forceinline__ uint32_t smem_to_u32(const void* p) {
    uint32_t a;
    asm("{ .reg .u64 t; cvta.to.shared.u64 t, %1; cvt.u32.u64 %0, t; }" : "=r"(a) : "l"(p));
    return a;
}

#define LDSM_X4(r, addr) \
    asm volatile("ldmatrix.sync.aligned.m8n8.x4.shared.b16 {%0,%1,%2,%3}, [%4];" \
        : "=r"((r)[0]), "=r"((r)[1]), "=r"((r)[2]), "=r"((r)[3]) : "r"(addr))
#define MMA16816(c, a0, a1, a2, a3, b0, b1) \
    asm volatile("mma.sync.aligned.m16n8k16.row.col.f32.f16.f16.f32 " \
        "{%0,%1,%2,%3}, {%4,%5,%6,%7}, {%8,%9}, {%0,%1,%2,%3};" \
        : "+f"((c)[0]), "+f"((c)[1]), "+f"((c)[2]), "+f"((c)[3]) \
        : "r"(a0), "r"(a1), "r"(a2), "r"(a3), "r"(b0), "r"(b1))

// mish(x) = x * (p^2-1)/(p^2+1), p = 1+e^x   (exact identity)
__device__ __forceinline__ float mish_f(float v) {
    float ev = __expf(fminf(v, 15.0f));
    float p  = 1.0f + ev;
    float p2 = p * p;
    return v * __fdividef(p2 - 1.0f, p2 + 1.0f);
}

__device__ __forceinline__ uint32_t pack2(float x, float y) {
    __half hx = __float2half_rn(x), hy = __float2half_rn(y);
    return ((uint32_t)__half_as_ushort(hy) << 16) | (uint32_t)__half_as_ushort(hx);
}

__global__ void __launch_bounds__(NTHREADS, 2)
edge_decoder_hmma(const float* __restrict__ z,
                  const void* __restrict__ edge_raw,
                  const float* __restrict__ W1,
                  const float* __restrict__ b1,
                  const float* __restrict__ W2,
                  const float* __restrict__ b2,
                  float* __restrict__ out,
                  int n_edges)
{
    extern __shared__ char smem[];
    const uint32_t sbase = smem_to_u32(smem);
    const int tid  = threadIdx.x;
    const int wid  = tid >> 5;
    const int lane = tid & 31;
    const int wm = (wid & 1) * 32;       // 2 m-warps x 32 rows
    const int wn = (wid >> 1) * 64;      // 4 n-warps x 64 cols

    const int is64 = g_edge_is_i64;
    const long long* e64 = (const long long*)edge_raw;
    const int*       e32 = (const int*)edge_raw;

    float2* bw2s = (float2*)(smem + BW_OFF);
    float*  part = (float*)(smem + PART_OFF);   // [64][4]

    // ---- prologue: W1 [256][128] -> fp16 SMEM, swizzled ----
    for (int c = tid; c < D_HID_ * 16; c += NTHREADS) {
        int n = c >> 4, ch = c & 15;
        const float4* wr = reinterpret_cast<const float4*>(W1) + n * 32 + ch * 2;
        float4 v0 = wr[0], v1 = wr[1];
        uint4 hi;
        hi.x = pack2(v0.x, v0.y); hi.y = pack2(v0.z, v0.w);
        hi.z = pack2(v1.x, v1.y); hi.w = pack2(v1.z, v1.w);
        uint32_t kb = (uint32_t)ch * 16;
        uint32_t sw = (uint32_t)n * 256 + (kb ^ (((uint32_t)n & 7) << 4));
        *reinterpret_cast<uint4*>(smem + W_HI_OFF + sw) = hi;
    }
    if (tid < D_HID_) { float2 t; t.x = b1[tid]; t.y = W2[tid]; bw2s[tid] = t; }
    const float bias2 = b2[0];
    __syncthreads();

    const int n_tiles = (n_edges + TILE_M - 1) / TILE_M;
    const int grid = gridDim.x;

    // coalesced gather mapping: 8 threads/edge (one 128B line per 8 lanes), 2 passes
    const int sub = tid & 7;     // 16B chunk within line group
    const int gm8 = tid >> 3;    // 0..31: local edge within pass

    for (int tile = blockIdx.x; tile < n_tiles; tile += grid) {
        const int e_base = tile * TILE_M;

        // ---- gather + product -> A fp16, swizzled, coalesced ----
        #pragma unroll
        for (int p = 0; p < 2; p++) {
            const int m = gm8 + p * 32;
            const int e = e_base + m;
            const uint32_t rb = (uint32_t)m * 256;
            const uint32_t swhalf = (uint32_t)(sub & 1) * 8;
            if (e < n_edges) {
                long long i0, i1;
                if (is64) { i0 = e64[e]; i1 = e64[n_edges + e]; }
                else      { i0 = e32[e]; i1 = e32[n_edges + e]; }
                const float4* z0 = reinterpret_cast<const float4*>(z) + i0 * 32 + sub;
                const float4* z1 = reinterpret_cast<const float4*>(z) + i1 * 32 + sub;
                #pragma unroll
                for (int c = 0; c < 4; c++) {
                    float4 a = z0[c * 8];
                    float4 b = z1[c * 8];
                    uint2 st;
                    st.x = pack2(a.x * b.x, a.y * b.y);
                    st.y = pack2(a.z * b.z, a.w * b.w);
                    uint32_t kb16 = (uint32_t)(c * 64 + (sub >> 1) * 16);
                    uint32_t sw = rb + (kb16 ^ (((uint32_t)m & 7) << 4)) + swhalf;
                    *reinterpret_cast<uint2*>(smem + A_HI_OFF + sw) = st;
                }
            } else {
                uint2 zz = {0, 0};
                #pragma unroll
                for (int c = 0; c < 4; c++) {
                    uint32_t kb16 = (uint32_t)(c * 64 + (sub >> 1) * 16);
                    uint32_t sw = rb + (kb16 ^ (((uint32_t)m & 7) << 4)) + swhalf;
                    *reinterpret_cast<uint2*>(smem + A_HI_OFF + sw) = zz;
                }
            }
        }
        __syncthreads();

        // ---- HMMA mainloop: warp tile 32(m) x 64(n), K=128, single fp16 term ----
        float C[2][8][4];
        #pragma unroll
        for (int mb = 0; mb < 2; mb++)
            #pragma unroll
            for (int n8 = 0; n8 < 8; n8++)
                #pragma unroll
                for (int q = 0; q < 4; q++) C[mb][n8][q] = 0.0f;

        {
            const int arow = wm + (lane & 15);
            // B x4 lane mapping: rows (lane>>4)*8 + (lane&7), k-half (lane>>3)&1
            const int brow = wn + ((lane >> 4) << 3) + (lane & 7);
            const int bksel = (lane >> 3) & 1;
            #pragma unroll
            for (int k16 = 0; k16 < 8; k16++) {
                uint32_t Ahi[2][4];
                uint32_t akb = (uint32_t)(k16 * 32 + (lane >> 4) * 16);
                uint32_t ad = sbase + A_HI_OFF + (uint32_t)arow * 256
                            + (akb ^ (((uint32_t)arow & 7) << 4));
                LDSM_X4(Ahi[0], ad);
                LDSM_X4(Ahi[1], ad + 16 * 256);

                uint32_t bkb = (uint32_t)(k16 * 32 + bksel * 16);
                uint32_t bd = sbase + W_HI_OFF + (uint32_t)brow * 256
                            + (bkb ^ (((uint32_t)brow & 7) << 4));
                #pragma unroll
                for (int n16 = 0; n16 < 4; n16++) {
                    uint32_t B4[4];
                    LDSM_X4(B4, bd + (uint32_t)n16 * 4096);   // 16 rows * 256B
                    MMA16816(C[0][2 * n16],     Ahi[0][0], Ahi[0][1], Ahi[0][2], Ahi[0][3], B4[0], B4[1]);
                    MMA16816(C[1][2 * n16],     Ahi[1][0], Ahi[1][1], Ahi[1][2], Ahi[1][3], B4[0], B4[1]);
                    MMA16816(C[0][2 * n16 + 1], Ahi[0][0], Ahi[0][1], Ahi[0][2], Ahi[0][3], B4[2], B4[3]);
                    MMA16816(C[1][2 * n16 + 1], Ahi[1][0], Ahi[1][1], Ahi[1][2], Ahi[1][3], B4[2], B4[3]);
                }
            }
        }

        // ---- epilogue: mish + W2-weighted reduce, in registers ----
        {
            float psum[4] = {0.f, 0.f, 0.f, 0.f};   // [mb*2 + half]
            #pragma unroll
            for (int n8 = 0; n8 < 8; n8++) {
                const int n = wn + n8 * 8 + 2 * (lane & 3);
                float2 bw0 = bw2s[n];
                float2 bw1 = bw2s[n + 1];
                #pragma unroll
                for (int mb = 0; mb < 2; mb++) {
                    const float* c = C[mb][n8];
                    psum[mb * 2 + 0] = fmaf(bw0.y, mish_f(c[0] + bw0.x),
                                       fmaf(bw1.y, mish_f(c[1] + bw1.x), psum[mb * 2 + 0]));
                    psum[mb * 2 + 1] = fmaf(bw0.y, mish_f(c[2] + bw0.x),
                                       fmaf(bw1.y, mish_f(c[3] + bw1.x), psum[mb * 2 + 1]));
                }
            }
            #pragma unroll
            for (int q = 0; q < 4; q++) {
                psum[q] += __shfl_xor_sync(0xffffffffu, psum[q], 1);
                psum[q] += __shfl_xor_sync(0xffffffffu, psum[q], 2);
            }
            if ((lane & 3) == 0) {
                const int r = lane >> 2;   // 0..7
                const int wcol = wid >> 1; // 0..3
                #pragma unroll
                for (int mb = 0; mb < 2; mb++) {
                    part[(wm + mb * 16 + r) * 4 + wcol]     = psum[mb * 2 + 0];
                    part[(wm + mb * 16 + r + 8) * 4 + wcol] = psum[mb * 2 + 1];
                }
            }
        }
        __syncthreads();

        if (tid < TILE_M) {
            const int e = e_base + tid;
            if (e < n_edges) {
                float s = (part[tid * 4 + 0] + part[tid * 4 + 1])
                        + (part[tid * 4 + 2] + part[tid * 4 + 3]) + bias2;
                out[e] = __fdividef(1.0f, 1.0f + __expf(-s));
            }
        }
        // next gather writes A only; part rewritten only after next barrier
    }
}

extern "C" void kernel_launch(void* const* d_in, const int* in_sizes, int n_in,
                              void* d_out, int out_size) {
    const float* zp  = (const float*)d_in[0];
    const void*  ep  = d_in[1];
    const float* W1p = (const float*)d_in[2];
    const float* b1p = (const float*)d_in[3];
    const float* W2p = (const float*)d_in[4];
    const float* b2p = (const float*)d_in[5];
    float* outp = (float*)d_out;
    const int n_edges = out_size;

    cudaFuncSetAttribute(edge_decoder_hmma,
                         cudaFuncAttributeMaxDynamicSharedMemorySize, SMEM_TOTAL);
    int sms = 148;
    cudaDeviceGetAttribute(&sms, cudaDevAttrMultiProcessorCount, 0);

    detect_edge_dtype<<<1, 32>>>((const unsigned int*)ep);
    edge_decoder_hmma<<<sms * 2, NTHREADS, SMEM_TOTAL>>>(
        zp, ep, W1p, b1p, W2p, b2p, outp, n_edges);
}

// round 10
// speedup vs baseline: 5.4349x; 1.0277x over previous
#include <cuda_runtime.h>
#include <cuda_fp16.h>
#include <cstdint>

#define D_IN_    128
#define D_HID_   256
#define TILE_M   64
#define NTHREADS 256

// ---- SMEM byte layout per CTA ----
#define A0_OFF     0         // A double buffer: 2 x (64 x 128 fp16 = 16 KB)
#define A_BUF_SZ   16384
#define W_HI_OFF   32768     // 256 x 128 fp16 = 64 KB
#define BW_OFF     98304     // float2[256] {b1, w2} = 2 KB
#define PART_OFF   100352    // 2 x float[64][4] = 2 KB
#define SMEM_TOTAL 102400

__device__ int g_edge_is_i64;

__global__ void detect_edge_dtype(const unsigned int* __restrict__ ew) {
    if (threadIdx.x == 0 && blockIdx.x == 0) {
        int is64 = 1;
        for (int i = 0; i < 256; i++)
            if (ew[2 * i + 1] != 0u) { is64 = 0; break; }
        g_edge_is_i64 = is64;
    }
}

__device__ __forceinline__ uint32_t smem_to_u32(const void* p) {
    uint32_t a;
    asm("{ .reg .u64 t; cvta.to.shared.u64 t, %1; cvt.u32.u64 %0, t; }" : "=r"(a) : "l"(p));
    return a;
}

#define LDSM_X4(r, addr) \
    asm volatile("ldmatrix.sync.aligned.m8n8.x4.shared.b16 {%0,%1,%2,%3}, [%4];" \
        : "=r"((r)[0]), "=r"((r)[1]), "=r"((r)[2]), "=r"((r)[3]) : "r"(addr))
#define MMA16816(c, a0, a1, a2, a3, b0, b1) \
    asm volatile("mma.sync.aligned.m16n8k16.row.col.f32.f16.f16.f32 " \
        "{%0,%1,%2,%3}, {%4,%5,%6,%7}, {%8,%9}, {%0,%1,%2,%3};" \
        : "+f"((c)[0]), "+f"((c)[1]), "+f"((c)[2]), "+f"((c)[3]) \
        : "r"(a0), "r"(a1), "r"(a2), "r"(a3), "r"(b0), "r"(b1))

__device__ __forceinline__ uint32_t pack2(float x, float y) {
    __half hx = __float2half_rn(x), hy = __float2half_rn(y);
    return ((uint32_t)__half_as_ushort(hy) << 16) | (uint32_t)__half_as_ushort(hx);
}

// gather 64 edges of tile into A buffer at dst (coalesced: 8 threads/edge, 2 passes)
__device__ __forceinline__ void gather_tile(char* smem, const float* __restrict__ z,
                                            const long long* __restrict__ e64,
                                            const int* __restrict__ e32, int is64,
                                            int e_base, int n_edges,
                                            int gm8, int sub, uint32_t dst)
{
    #pragma unroll
    for (int p = 0; p < 2; p++) {
        const int m = gm8 + p * 32;
        const int e = e_base + m;
        const uint32_t rb = (uint32_t)m * 256;
        const uint32_t swhalf = (uint32_t)(sub & 1) * 8;
        if (e < n_edges) {
            long long i0, i1;
            if (is64) { i0 = e64[e]; i1 = e64[n_edges + e]; }
            else      { i0 = e32[e]; i1 = e32[n_edges + e]; }
            const float4* z0 = reinterpret_cast<const float4*>(z) + i0 * 32 + sub;
            const float4* z1 = reinterpret_cast<const float4*>(z) + i1 * 32 + sub;
            #pragma unroll
            for (int c = 0; c < 4; c++) {
                float4 a = z0[c * 8];
                float4 b = z1[c * 8];
                uint2 st;
                st.x = pack2(a.x * b.x, a.y * b.y);
                st.y = pack2(a.z * b.z, a.w * b.w);
                uint32_t kb16 = (uint32_t)(c * 64 + (sub >> 1) * 16);
                uint32_t sw = rb + (kb16 ^ (((uint32_t)m & 7) << 4)) + swhalf;
                *reinterpret_cast<uint2*>(smem + dst + sw) = st;
            }
        } else {
            uint2 zz = {0, 0};
            #pragma unroll
            for (int c = 0; c < 4; c++) {
                uint32_t kb16 = (uint32_t)(c * 64 + (sub >> 1) * 16);
                uint32_t sw = rb + (kb16 ^ (((uint32_t)m & 7) << 4)) + swhalf;
                *reinterpret_cast<uint2*>(smem + dst + sw) = zz;
            }
        }
    }
}

__global__ void __launch_bounds__(NTHREADS, 2)
edge_decoder_hmma(const float* __restrict__ z,
                  const void* __restrict__ edge_raw,
                  const float* __restrict__ W1,
                  const float* __restrict__ b1,
                  const float* __restrict__ W2,
                  const float* __restrict__ b2,
                  float* __restrict__ out,
                  int n_edges)
{
    extern __shared__ char smem[];
    const uint32_t sbase = smem_to_u32(smem);
    const int tid  = threadIdx.x;
    const int wid  = tid >> 5;
    const int lane = tid & 31;
    const int wm = (wid & 1) * 32;       // 2 m-warps x 32 rows
    const int wn = (wid >> 1) * 64;      // 4 n-warps x 64 cols

    const int is64 = g_edge_is_i64;
    const long long* e64 = (const long long*)edge_raw;
    const int*       e32 = (const int*)edge_raw;

    float2* bw2s = (float2*)(smem + BW_OFF);

    // ---- prologue: W1 [256][128] -> fp16 SMEM, swizzled ----
    for (int c = tid; c < D_HID_ * 16; c += NTHREADS) {
        int n = c >> 4, ch = c & 15;
        const float4* wr = reinterpret_cast<const float4*>(W1) + n * 32 + ch * 2;
        float4 v0 = wr[0], v1 = wr[1];
        uint4 hi;
        hi.x = pack2(v0.x, v0.y); hi.y = pack2(v0.z, v0.w);
        hi.z = pack2(v1.x, v1.y); hi.w = pack2(v1.z, v1.w);
        uint32_t kb = (uint32_t)ch * 16;
        uint32_t sw = (uint32_t)n * 256 + (kb ^ (((uint32_t)n & 7) << 4));
        *reinterpret_cast<uint4*>(smem + W_HI_OFF + sw) = hi;
    }
    if (tid < D_HID_) { float2 t; t.x = b1[tid]; t.y = W2[tid]; bw2s[tid] = t; }
    const float bias2 = b2[0];

    const int n_tiles = (n_edges + TILE_M - 1) / TILE_M;
    const int grid = gridDim.x;
    const int bid = blockIdx.x;

    const int sub = tid & 7;     // 16B chunk within 128B line
    const int gm8 = tid >> 3;    // 0..31 edge within pass

    // ---- gather tile 0 -> A[0] ----
    if (bid < n_tiles)
        gather_tile(smem, z, e64, e32, is64, bid * TILE_M, n_edges, gm8, sub, A0_OFF);
    __syncthreads();

    int i = 0;
    for (int tile = bid; tile < n_tiles; tile += grid, i++) {
        const int abuf = i & 1;
        const uint32_t aoff = A0_OFF + (uint32_t)abuf * A_BUF_SZ;
        const int e_base = tile * TILE_M;

        // ---- HMMA: warp tile 32(m) x 64(n), K=128 ----
        float C[2][8][4];
        #pragma unroll
        for (int mb = 0; mb < 2; mb++)
            #pragma unroll
            for (int n8 = 0; n8 < 8; n8++)
                #pragma unroll
                for (int q = 0; q < 4; q++) C[mb][n8][q] = 0.0f;
        {
            const int arow = wm + (lane & 15);
            const int brow = wn + ((lane >> 4) << 3) + (lane & 7);
            const int bksel = (lane >> 3) & 1;
            #pragma unroll
            for (int k16 = 0; k16 < 8; k16++) {
                uint32_t Ahi[2][4];
                uint32_t akb = (uint32_t)(k16 * 32 + (lane >> 4) * 16);
                uint32_t ad = sbase + aoff + (uint32_t)arow * 256
                            + (akb ^ (((uint32_t)arow & 7) << 4));
                LDSM_X4(Ahi[0], ad);
                LDSM_X4(Ahi[1], ad + 16 * 256);

                uint32_t bkb = (uint32_t)(k16 * 32 + bksel * 16);
                uint32_t bd = sbase + W_HI_OFF + (uint32_t)brow * 256
                            + (bkb ^ (((uint32_t)brow & 7) << 4));
                #pragma unroll
                for (int n16 = 0; n16 < 4; n16++) {
                    uint32_t B4[4];
                    LDSM_X4(B4, bd + (uint32_t)n16 * 4096);
                    MMA16816(C[0][2 * n16],     Ahi[0][0], Ahi[0][1], Ahi[0][2], Ahi[0][3], B4[0], B4[1]);
                    MMA16816(C[1][2 * n16],     Ahi[1][0], Ahi[1][1], Ahi[1][2], Ahi[1][3], B4[0], B4[1]);
                    MMA16816(C[0][2 * n16 + 1], Ahi[0][0], Ahi[0][1], Ahi[0][2], Ahi[0][3], B4[2], B4[3]);
                    MMA16816(C[1][2 * n16 + 1], Ahi[1][0], Ahi[1][1], Ahi[1][2], Ahi[1][3], B4[2], B4[3]);
                }
            }
        }

        // ---- prefetch-gather tile i+1 -> A[abuf^1] (overlaps epilogue below) ----
        {
            const int ntile = tile + grid;
            if (ntile < n_tiles)
                gather_tile(smem, z, e64, e32, is64, ntile * TILE_M, n_edges,
                            gm8, sub, A0_OFF + (uint32_t)(abuf ^ 1) * A_BUF_SZ);
        }

        // ---- epilogue: mish (pairwise rcp) + W2-weighted reduce ----
        float* part = (float*)(smem + PART_OFF + abuf * 1024);
        {
            float psum[4] = {0.f, 0.f, 0.f, 0.f};
            #pragma unroll
            for (int n8 = 0; n8 < 8; n8++) {
                const int n = wn + n8 * 8 + 2 * (lane & 3);
                float2 bw0 = bw2s[n];
                float2 bw1 = bw2s[n + 1];
                #pragma unroll
                for (int mb = 0; mb < 2; mb++) {
                    const float* c = C[mb][n8];
                    #pragma unroll
                    for (int h = 0; h < 2; h++) {
                        float y0 = c[2 * h]     + bw0.x;
                        float y1 = c[2 * h + 1] + bw1.x;
                        float ev0 = __expf(fminf(y0, 15.0f));
                        float ev1 = __expf(fminf(y1, 15.0f));
                        float p0 = 1.0f + ev0, p1 = 1.0f + ev1;
                        float p20 = p0 * p0,   p21 = p1 * p1;
                        float n0 = p20 - 1.0f, d0 = p20 + 1.0f;
                        float n1 = p21 - 1.0f, d1 = p21 + 1.0f;
                        float r = __fdividef(1.0f, d0 * d1);
                        float m0 = y0 * n0 * (d1 * r);
                        float m1 = y1 * n1 * (d0 * r);
                        psum[mb * 2 + h] = fmaf(bw0.y, m0, fmaf(bw1.y, m1, psum[mb * 2 + h]));
                    }
                }
            }
            #pragma unroll
            for (int q = 0; q < 4; q++) {
                psum[q] += __shfl_xor_sync(0xffffffffu, psum[q], 1);
                psum[q] += __shfl_xor_sync(0xffffffffu, psum[q], 2);
            }
            if ((lane & 3) == 0) {
                const int r = lane >> 2;   // 0..7
                const int wcol = wid >> 1; // 0..3
                #pragma unroll
                for (int mb = 0; mb < 2; mb++) {
                    part[(wm + mb * 16 + r) * 4 + wcol]     = psum[mb * 2 + 0];
                    part[(wm + mb * 16 + r + 8) * 4 + wcol] = psum[mb * 2 + 1];
                }
            }
        }
        __syncthreads();   // part ready; A[abuf^1] ready for next iter

        if (tid < TILE_M) {
            const int e = e_base + tid;
            if (e < n_edges) {
                float s = (part[tid * 4 + 0] + part[tid * 4 + 1])
                        + (part[tid * 4 + 2] + part[tid * 4 + 3]) + bias2;
                out[e] = __fdividef(1.0f, 1.0f + __expf(-s));
            }
        }
    }
}

extern "C" void kernel_launch(void* const* d_in, const int* in_sizes, int n_in,
                              void* d_out, int out_size) {
    const float* zp  = (const float*)d_in[0];
    const void*  ep  = d_in[1];
    const float* W1p = (const float*)d_in[2];
    const float* b1p = (const float*)d_in[3];
    const float* W2p = (const float*)d_in[4];
    const float* b2p = (const float*)d_in[5];
    float* outp = (float*)d_out;
    const int n_edges = out_size;

    cudaFuncSetAttribute(edge_decoder_hmma,
                         cudaFuncAttributeMaxDynamicSharedMemorySize, SMEM_TOTAL);
    int sms = 148;
    cudaDeviceGetAttribute(&sms, cudaDevAttrMultiProcessorCount, 0);

    detect_edge_dtype<<<1, 32>>>((const unsigned int*)ep);
    edge_decoder_hmma<<<sms * 2, NTHREADS, SMEM_TOTAL>>>(
        zp, ep, W1p, b1p, W2p, b2p, outp, n_edges);
}